// round 10
// baseline (speedup 1.0000x reference)
#include <cuda_runtime.h>
#include <cstdint>
#include <cstddef>

// B=4, N=256, E=512.  Row-band decomposition: every output row i depends only
// on G[i,:] and inputs, so the problem splits into 64 independent band groups
// (batch b x 16-row band q).  Each group = 4 CTAs (part p = 0..3) that split
// the column dimension; they sync among themselves (4-arrival flag in L2),
// never chip-wide.  Per group chain:
//   G[band, n]  = X_band @ X^T            (k = 512; part p owns n-cols 64p..)
//   S[band, p'] = L( L(G) @ Kw )          (k = n <= i; A-masked, C-masked)
//   T[band, n'] = L( S @ Qw^T )           (k = p' <= i; C-masked)
//   F[band, e]  = T @ X                   (k = n <= i; part owns e-cols 128p..)
//   out = x * (1 + F - x.F)               (avg reduced across the 4 parts)
// GEMMs: mma.sync m16n8k8 tf32, 2-way split (3 mma): err ~2^-22.
// G/S/T parts whose columns exceed the band's diagonal are skipped (their
// values are provably never read).  Deterministic: fixed schedule, fixed
// reduction order, sync counters reset by the last CTA of each group.

#define NN_   256
#define EE_   512
#define BM    16
#define NGRP  64            // 4 batches x 16 bands
#define GRID  (NGRP * 4)    // 256 CTAs

__device__ __align__(16) float g_G[NGRP][BM][NN_];
__device__ __align__(16) float g_S[NGRP][BM][NN_];
__device__ __align__(16) float g_T[NGRP][BM][NN_];
__device__ __align__(16) float g_PAV[NGRP][4][BM];
__device__ unsigned g_cnt[NGRP][8];   // [0..3] syncs, [4] fin

__device__ __forceinline__ unsigned f2tf(float x) {
    unsigned r;
    asm("cvt.rna.tf32.f32 %0, %1;" : "=r"(r) : "f"(x));
    return r;
}
__device__ __forceinline__ void mma_tf32(float* c, const unsigned* a,
                                         unsigned b0, unsigned b1) {
    asm("mma.sync.aligned.m16n8k8.row.col.f32.tf32.tf32.f32 "
        "{%0,%1,%2,%3},{%4,%5,%6,%7},{%8,%9},{%0,%1,%2,%3};"
        : "+f"(c[0]), "+f"(c[1]), "+f"(c[2]), "+f"(c[3])
        : "r"(a[0]), "r"(a[1]), "r"(a[2]), "r"(a[3]), "r"(b0), "r"(b1));
}

// 4-CTA group sync (monotonic within a launch; reset at kernel end).
__device__ __forceinline__ void group_sync(int g, int s) {
    __syncthreads();
    if (threadIdx.x == 0) {
        __threadfence();
        atomicAdd(&g_cnt[g][s], 1u);
        while (*(volatile unsigned*)&g_cnt[g][s] < 4u) { }
        __threadfence();
    }
    __syncthreads();
}

__global__ __launch_bounds__(128, 2)
void replicator_band(const float* __restrict__ X,
                     const float* __restrict__ Qw,
                     const float* __restrict__ Kw,
                     float* __restrict__ out)
{
    __shared__ float Xb[BM][EE_ + 4];        // X band rows (33 KB)
    __shared__ float As[2][16][BM + 2];      // staged A, k-major
    __shared__ float Bs[2][16][132];         // staged B, k-major
    __shared__ float pav[4][BM];
    __shared__ float avs[BM];

    const int tid  = threadIdx.x;
    const int lane = tid & 31;
    const int warp = tid >> 5;
    const int lr   = lane >> 2;
    const int lc   = lane & 3;

    const int part = blockIdx.x & 3;
    const int g    = blockIdx.x >> 2;
    const int b    = g >> 4;
    const int q    = g & 15;
    const int i0   = q * BM;
    const float* Xbat = X + (size_t)b * NN_ * EE_;
    const bool act = part <= (q >> 2);       // G/S/T cols needed only if <= diag
    const int nch  = q + 1;                  // k chunks (16 each) for S/T/F

    // ---- X band -> smem
    for (int t = tid; t < BM * (EE_ / 4); t += 128) {
        const int r = t >> 7, c = (t & 127) << 2;
        *(float4*)&Xb[r][c] = *(const float4*)&Xbat[(size_t)(i0 + r) * EE_ + c];
    }
    __syncthreads();

    // ---------- staging lambdas ----------
    const int jj  = tid >> 2;            // 0..31 (NT row; +32 on it=1)
    const int lc4 = (tid & 3) << 2;
    float4 rbNT[2];
    auto ldNT = [&](const float* src, int ldb, int kg) {
        rbNT[0] = *(const float4*)&src[(size_t)jj * ldb + kg + lc4];
        rbNT[1] = *(const float4*)&src[(size_t)(jj + 32) * ldb + kg + lc4];
    };
    auto stNT = [&](int buf) {
        #pragma unroll
        for (int it = 0; it < 2; it++) {
            const float4 v = rbNT[it];
            const int j = jj + it * 32;
            Bs[buf][lc4 + 0][j] = v.x;
            Bs[buf][lc4 + 1][j] = v.y;
            Bs[buf][lc4 + 2][j] = v.z;
            Bs[buf][lc4 + 3][j] = v.w;
        }
    };
    const int kr8 = tid >> 4;            // 0..7 (NN64 k row; +8 on it=1)
    const int jc4 = (tid & 15) << 2;
    float4 rbNN[2];
    auto ldNN64 = [&](const float* src, int ldb, int cb, int kg) {
        rbNN[0] = *(const float4*)&src[(size_t)(kg + kr8) * ldb + cb + jc4];
        rbNN[1] = *(const float4*)&src[(size_t)(kg + kr8 + 8) * ldb + cb + jc4];
    };
    auto stNN64 = [&](int buf) {
        *(float4*)&Bs[buf][kr8][jc4]     = rbNN[0];
        *(float4*)&Bs[buf][kr8 + 8][jc4] = rbNN[1];
    };
    const int kr4 = tid >> 5;            // 0..3 (NN128; 4 its of +4)
    const int jc2 = (tid & 31) << 2;
    float4 rbF[4];
    auto ldNN128 = [&](const float* src, int cb, int kg) {
        #pragma unroll
        for (int it = 0; it < 4; it++)
            rbF[it] = *(const float4*)&src[(size_t)(kg + kr4 + it * 4) * EE_ + cb + jc2];
    };
    auto stNN128 = [&](int buf) {
        #pragma unroll
        for (int it = 0; it < 4; it++)
            *(float4*)&Bs[buf][kr4 + it * 4][jc2] = rbF[it];
    };
    const int arw = tid >> 3;            // 0..15 (A-stage row)
    const int akc = (tid & 7) << 1;      // 0..14
    float2 raA;
    auto ldA = [&](const float* src, int kg) {
        raA = *(const float2*)&src[arw * NN_ + kg + akc];
    };
    auto stA = [&](int buf, bool maskA, int kg) {
        float2 v = raA;
        if (maskA) {
            const int i = i0 + arw;
            if (kg + akc > i)     v.x = 0.f;
            if (kg + akc + 1 > i) v.y = 0.f;
        }
        As[buf][akc][arw]     = v.x;
        As[buf][akc + 1][arw] = v.y;
    };

    // ---------- mma lambdas ----------
    auto do_mma2 = [&](float (&ac)[2][4], int buf, bool fromXb, int eabs) {
        #pragma unroll
        for (int kk = 0; kk < 16; kk += 8) {
            unsigned ahi[4], alo[4];
            #pragma unroll
            for (int r = 0; r < 4; r++) {
                const int krow = kk + lc + ((r >> 1) << 2);
                const int arow = lr + ((r & 1) << 3);
                const float v = fromXb ? Xb[arow][eabs + krow]
                                       : As[buf][krow][arow];
                const unsigned h = f2tf(v);
                ahi[r] = h;
                alo[r] = f2tf(v - __uint_as_float(h));
            }
            #pragma unroll
            for (int u = 0; u < 2; u++) {
                const int c0 = warp * 16 + u * 8 + lr;
                const float v0 = Bs[buf][kk + lc][c0];
                const float v1 = Bs[buf][kk + lc + 4][c0];
                const unsigned bh0 = f2tf(v0), bh1 = f2tf(v1);
                const unsigned bl0 = f2tf(v0 - __uint_as_float(bh0));
                const unsigned bl1 = f2tf(v1 - __uint_as_float(bh1));
                mma_tf32(ac[u], ahi, bh0, bh1);
                mma_tf32(ac[u], ahi, bl0, bl1);
                mma_tf32(ac[u], alo, bh0, bh1);
            }
        }
    };
    auto do_mma4 = [&](float (&ac)[4][4], int buf) {
        #pragma unroll
        for (int kk = 0; kk < 16; kk += 8) {
            unsigned ahi[4], alo[4];
            #pragma unroll
            for (int r = 0; r < 4; r++) {
                const int krow = kk + lc + ((r >> 1) << 2);
                const int arow = lr + ((r & 1) << 3);
                const float v = As[buf][krow][arow];
                const unsigned h = f2tf(v);
                ahi[r] = h;
                alo[r] = f2tf(v - __uint_as_float(h));
            }
            #pragma unroll
            for (int u = 0; u < 4; u++) {
                const int c0 = warp * 32 + u * 8 + lr;
                const float v0 = Bs[buf][kk + lc][c0];
                const float v1 = Bs[buf][kk + lc + 4][c0];
                const unsigned bh0 = f2tf(v0), bh1 = f2tf(v1);
                const unsigned bl0 = f2tf(v0 - __uint_as_float(bh0));
                const unsigned bl1 = f2tf(v1 - __uint_as_float(bh1));
                mma_tf32(ac[u], ahi, bh0, bh1);
                mma_tf32(ac[u], ahi, bl0, bl1);
                mma_tf32(ac[u], alo, bh0, bh1);
            }
        }
    };
    // store a 64-col band result (per warp 16 cols), optional tril mask
    auto store_band = [&](float* dst, int cb, float (&ac)[2][4], bool maskC) {
        #pragma unroll
        for (int u = 0; u < 2; u++) {
            const int jb = cb + warp * 16 + u * 8 + 2 * lc;
            #pragma unroll
            for (int h = 0; h < 2; h++) {
                const int il = lr + h * 8;
                float2 o = make_float2(ac[u][2 * h], ac[u][2 * h + 1]);
                if (maskC) {
                    const int i = i0 + il;
                    if (jb > i)     o.x = 0.f;
                    if (jb + 1 > i) o.y = 0.f;
                }
                *(float2*)&dst[il * NN_ + jb] = o;
            }
        }
    };

    float acc2[2][4];

    // ================= G: cols [64p, 64p+64), k = 512 =================
    if (act) {
        const int n0 = part * 64;
        const float* Bsrc = Xbat + (size_t)n0 * EE_;
        #pragma unroll
        for (int u = 0; u < 2; u++)
            #pragma unroll
            for (int v = 0; v < 4; v++) acc2[u][v] = 0.f;
        ldNT(Bsrc, EE_, 0);
        stNT(0);
        __syncthreads();
        int buf = 0;
        #pragma unroll 1
        for (int ch = 0; ch < 32; ch++) {
            if (ch + 1 < 32) ldNT(Bsrc, EE_, (ch + 1) * 16);
            do_mma2(acc2, buf, true, ch * 16);
            if (ch + 1 < 32) { stNT(buf ^ 1); __syncthreads(); buf ^= 1; }
        }
        store_band(&g_G[g][0][0], n0, acc2, false);
    }
    group_sync(g, 0);

    // ================= S: cols [64p,+64), k = n <= i =================
    if (act) {
        const int p0 = part * 64;
        #pragma unroll
        for (int u = 0; u < 2; u++)
            #pragma unroll
            for (int v = 0; v < 4; v++) acc2[u][v] = 0.f;
        ldA(&g_G[g][0][0], 0);
        ldNN64(Kw, NN_, p0, 0);
        stA(0, true, 0);
        stNN64(0);
        __syncthreads();
        int buf = 0;
        #pragma unroll 1
        for (int ch = 0; ch < nch; ch++) {
            if (ch + 1 < nch) { ldA(&g_G[g][0][0], (ch + 1) * 16);
                                ldNN64(Kw, NN_, p0, (ch + 1) * 16); }
            do_mma2(acc2, buf, false, 0);
            if (ch + 1 < nch) { stA(buf ^ 1, true, (ch + 1) * 16);
                                stNN64(buf ^ 1); __syncthreads(); buf ^= 1; }
        }
        store_band(&g_S[g][0][0], p0, acc2, true);
    }
    group_sync(g, 1);

    // ================= T: cols [64p,+64), k = p' <= i =================
    if (act) {
        const int n0 = part * 64;
        const float* Bsrc = Qw + (size_t)n0 * NN_;
        #pragma unroll
        for (int u = 0; u < 2; u++)
            #pragma unroll
            for (int v = 0; v < 4; v++) acc2[u][v] = 0.f;
        ldA(&g_S[g][0][0], 0);
        ldNT(Bsrc, NN_, 0);
        stA(0, false, 0);
        stNT(0);
        __syncthreads();
        int buf = 0;
        #pragma unroll 1
        for (int ch = 0; ch < nch; ch++) {
            if (ch + 1 < nch) { ldA(&g_S[g][0][0], (ch + 1) * 16);
                                ldNT(Bsrc, NN_, (ch + 1) * 16); }
            do_mma2(acc2, buf, false, 0);
            if (ch + 1 < nch) { stA(buf ^ 1, false, (ch + 1) * 16);
                                stNT(buf ^ 1); __syncthreads(); buf ^= 1; }
        }
        store_band(&g_T[g][0][0], n0, acc2, true);
    }
    group_sync(g, 2);

    // ================= F: e-cols [128p,+128), k = n <= i (regs) ==========
    float accF[4][4];
    #pragma unroll
    for (int u = 0; u < 4; u++)
        #pragma unroll
        for (int v = 0; v < 4; v++) accF[u][v] = 0.f;
    {
        const int e0 = part * 128;
        ldA(&g_T[g][0][0], 0);
        ldNN128(Xbat, e0, 0);
        stA(0, false, 0);
        stNN128(0);
        __syncthreads();
        int buf = 0;
        #pragma unroll 1
        for (int ch = 0; ch < nch; ch++) {
            if (ch + 1 < nch) { ldA(&g_T[g][0][0], (ch + 1) * 16);
                                ldNN128(Xbat, e0, (ch + 1) * 16); }
            do_mma4(accF, buf);
            if (ch + 1 < nch) { stA(buf ^ 1, false, (ch + 1) * 16);
                                stNN128(buf ^ 1); __syncthreads(); buf ^= 1; }
        }
    }

    // ---- partial avg over this part's e-slice
    {
        const int e0 = part * 128;
        float s0 = 0.f, s1 = 0.f;
        #pragma unroll
        for (int u = 0; u < 4; u++) {
            const int e = e0 + warp * 32 + u * 8 + 2 * lc;
            s0 += accF[u][0] * Xb[lr][e]     + accF[u][1] * Xb[lr][e + 1];
            s1 += accF[u][2] * Xb[lr + 8][e] + accF[u][3] * Xb[lr + 8][e + 1];
        }
        s0 += __shfl_xor_sync(0xffffffffu, s0, 1);
        s0 += __shfl_xor_sync(0xffffffffu, s0, 2);
        s1 += __shfl_xor_sync(0xffffffffu, s1, 1);
        s1 += __shfl_xor_sync(0xffffffffu, s1, 2);
        if (lc == 0) { pav[warp][lr] = s0; pav[warp][lr + 8] = s1; }
        __syncthreads();
        if (tid < BM)
            g_PAV[g][part][tid] = pav[0][tid] + pav[1][tid]
                                + pav[2][tid] + pav[3][tid];
    }
    group_sync(g, 3);

    if (tid < BM)
        avs[tid] = g_PAV[g][0][tid] + g_PAV[g][1][tid]
                 + g_PAV[g][2][tid] + g_PAV[g][3][tid];
    __syncthreads();

    // ---- out = x * (1 + F - avg)
    {
        const int e0 = part * 128;
        const float a0 = avs[lr];
        const float a1 = avs[lr + 8];
        float* outb = out + ((size_t)b * NN_ + i0) * EE_;
        #pragma unroll
        for (int u = 0; u < 4; u++) {
            const int e = e0 + warp * 32 + u * 8 + 2 * lc;
            float2 o0, o1;
            o0.x = Xb[lr][e]     * (1.f + accF[u][0] - a0);
            o0.y = Xb[lr][e + 1] * (1.f + accF[u][1] - a0);
            o1.x = Xb[lr + 8][e]     * (1.f + accF[u][2] - a1);
            o1.y = Xb[lr + 8][e + 1] * (1.f + accF[u][3] - a1);
            *(float2*)&outb[(size_t)lr * EE_ + e]       = o0;
            *(float2*)&outb[(size_t)(lr + 8) * EE_ + e] = o1;
        }
    }

    // ---- reset group counters (last of the 4 CTAs)
    __syncthreads();
    if (tid == 0) {
        if (atomicAdd(&g_cnt[g][4], 1u) == 3u) {
            g_cnt[g][0] = 0; g_cnt[g][1] = 0;
            g_cnt[g][2] = 0; g_cnt[g][3] = 0;
            __threadfence();
            g_cnt[g][4] = 0;
        }
    }
}

extern "C" void kernel_launch(void* const* d_in, const int* in_sizes, int n_in,
                              void* d_out, int out_size)
{
    const float* X  = (const float*)d_in[0];   // (4,256,512)
    const float* Qw = (const float*)d_in[1];   // (256,256)
    const float* Kw = (const float*)d_in[2];   // (256,256)
    float* out = (float*)d_out;                // (4,256,512)

    replicator_band<<<GRID, 128>>>(X, Qw, Kw, out);
}